// round 14
// baseline (speedup 1.0000x reference)
#include <cuda_runtime.h>
#include <cstdint>

// ---------------------------------------------------------------------------
// WaveBNN R14: R11 base + (1) fc1 weight words staged in smem, FC reads via
// broadcast LDS.128 (2-cyc floor vs LDG 4-cyc), (2) activation bits kept in
// REGISTERS via compile-time group indices (frees 23KB smem), (3) FC unroll 4.
// Fused, 1 thread/row, warp-private cp.async double buffering, one barrier.
// ---------------------------------------------------------------------------

#define OUTCH 16
#define NWORDS 45
#define NWPAD 48
#define FC1N 64
#define FC2N 5
#define RPB 32               // rows per warp
#define TPB 128              // 4 warps -> 128 rows per block
#define XST 27               // staging stride (odd -> conflict-free scalar LDS)
#define NBITBLK 384          // prep: 3072 word-warps / 8 warps per block
#define STG_BYTES (4 * 2 * RPB * XST * 4)           // 27648
#define WB_BYTES  (FC1N * NWPAD * 4)                // 12288
#define DYN_SMEM  (STG_BYTES + WB_BYTES)            // 39936

// device scratch (no allocation allowed)
__device__ uint32_t           d_wbits[FC1N * NWPAD];
__device__ unsigned long long d_convWp[4 * 8 * 3];   // packed (W[2p],W[2p+1])*A
__device__ unsigned long long d_convBp[4 * 8];       // packed folded bias pairs
__device__ float2             d_AB1[FC1N];           // (A1, B1) per j
__device__ float              d_w2t[FC1N * 8];       // transposed fc2 w, padded

// ---------------- PTX helpers ----------------
__device__ __forceinline__ unsigned long long pk2(float lo, float hi) {
    unsigned long long d;
    asm("mov.b64 %0, {%1, %2};" : "=l"(d) : "f"(lo), "f"(hi));
    return d;
}
__device__ __forceinline__ void unpk2(unsigned long long v, float& lo, float& hi) {
    asm("mov.b64 {%0, %1}, %2;" : "=f"(lo), "=f"(hi) : "l"(v));
}
__device__ __forceinline__ unsigned long long ffma2(
    unsigned long long a, unsigned long long b, unsigned long long c) {
    unsigned long long d;
    asm("fma.rn.f32x2 %0, %1, %2, %3;" : "=l"(d) : "l"(a), "l"(b), "l"(c));
    return d;
}
__device__ __forceinline__ void cp_async4(uint32_t saddr, const float* gaddr) {
    asm volatile("cp.async.ca.shared.global [%0], [%1], 4;" :: "r"(saddr), "l"(gaddr));
}
#define CP_COMMIT() asm volatile("cp.async.commit_group;")
#define CP_WAIT1()  asm volatile("cp.async.wait_group 1;")
#define CP_WAIT0()  asm volatile("cp.async.wait_group 0;")

// ---------------------------------------------------------------------------
// prep: blocks 0..NBITBLK-1 pack fc1 bits via ballot; block NBITBLK folds
// BN constants + packs AB1 + transposes fc2w.
// ---------------------------------------------------------------------------
__global__ void prep_all(
    const float* w0, const float* g0, const float* b0, const float* m0, const float* v0,
    const float* w1, const float* g1b, const float* b1b, const float* m1b, const float* v1b,
    const float* w2, const float* g2, const float* b2, const float* m2, const float* v2,
    const float* w3, const float* g3, const float* b3, const float* m3, const float* v3,
    const float* g1, const float* b1, const float* m1, const float* v1,
    const float* fc1w, const float* fc2w)
{
    int tid = threadIdx.x;
    if (blockIdx.x == NBITBLK) {
        if (tid < 64) {
            int br = tid >> 4, c = tid & 15;
            int p = c >> 1, h = c & 1;
            const float* ws[4] = {w0, w1, w2, w3};
            const float* gs[4] = {g0, g1b, g2, g3};
            const float* bs[4] = {b0, b1b, b2, b3};
            const float* ms[4] = {m0, m1b, m2, m3};
            const float* vs[4] = {v0, v1b, v2, v3};
            double A = (double)gs[br][c] * rsqrt((double)vs[br][c] + 1e-5);
            float Af = (float)A;
            float* bp = (float*)d_convBp;
            bp[(br * 8 + p) * 2 + h] = (float)((double)bs[br][c] - (double)ms[br][c] * A);
            float* wp = (float*)d_convWp;
            #pragma unroll
            for (int k = 0; k < 3; k++) {
                float wv = ws[br][c * 3 + k];
                float s = (wv > 0.f) ? 1.f : ((wv < 0.f) ? -1.f : 0.f);
                wp[(((br * 8 + p) * 3) + k) * 2 + h] = s * Af;
            }
        } else if (tid < 128) {
            int j = tid - 64;
            double A = (double)g1[j] * rsqrt((double)v1[j] + 1e-5);
            d_AB1[j] = make_float2((float)A,
                                   (float)((double)b1[j] - (double)m1[j] * A));
        }
        for (int idx = tid; idx < FC1N * 8; idx += 256) {
            int j = idx >> 3, i = idx & 7;
            d_w2t[idx] = (i < FC2N) ? fc2w[i * FC1N + j] : 0.f;
        }
        return;
    }
    // bit packing: global warp = (j, wi); lane = bit index
    int gwarp = blockIdx.x * 8 + (tid >> 5);
    int lane = tid & 31;
    if (gwarp >= FC1N * NWPAD) return;
    int j = gwarp / NWPAD, wi = gwarp % NWPAD;
    int gb = wi * 32 + lane;
    bool pred = false;
    if (gb < 1440) {
        const int OFF[4] = {0, 176, 352, 704};
        const int LPa[4] = {11, 11, 22, 46};
        int grp = gb >> 4, c = gb & 15, br, t;
        if (grp < 11)      { br = 0; t = grp; }
        else if (grp < 22) { br = 1; t = grp - 11; }
        else if (grp < 44) { br = 2; t = grp - 22; }
        else               { br = 3; t = grp - 44; }
        int col = OFF[br] + c * LPa[br] + t;
        pred = fc1w[j * 1440 + col] > 0.f;
    }
    uint32_t wrd = __ballot_sync(0xffffffffu, pred);
    if (lane == 0) d_wbits[j * NWPAD + wi] = wrd;
}

// ---------------------------------------------------------------------------
// fused kernel helpers
// ---------------------------------------------------------------------------
// warp-scope stage of RPB x COLS slab (pitch L) into sdst (stride XST)
template<int COLS, int L>
__device__ __forceinline__ void stage32(
    float* __restrict__ sdst, const float* __restrict__ xg,
    int rowbase, int c0, int lane, int rows)
{
    uint32_t sb = (uint32_t)__cvta_generic_to_shared(sdst);
    #pragma unroll
    for (int i = lane; i < RPB * COLS; i += 32) {
        int r = i / COLS, c = i - r * COLS;
        int rr = min(rowbase + r, rows - 1);
        cp_async4(sb + (uint32_t)(r * XST + c) * 4, xg + (size_t)rr * L + c0 + c);
    }
}

__device__ __forceinline__ void load_branch_g(
    int br, unsigned long long (&Wp)[8][3], unsigned long long (&Bp)[8])
{
    #pragma unroll
    for (int p = 0; p < 8; p++) {
        Wp[p][0] = d_convWp[(br * 8 + p) * 3 + 0];
        Wp[p][1] = d_convWp[(br * 8 + p) * 3 + 1];
        Wp[p][2] = d_convWp[(br * 8 + p) * 3 + 2];
        Bp[p]    = d_convBp[br * 8 + p];
    }
}

// conv NP pooled groups, bits -> REGISTER array (compile-time indices).
template<int NP, int GBASE>
__device__ __forceinline__ void run_chunk(
    const float* __restrict__ sx,
    const unsigned long long (&Wp)[8][3], const unsigned long long (&Bp)[8],
    uint32_t (&a)[NWORDS], uint32_t& acc)
{
    float xa = sx[0], xb = sx[1];
    unsigned long long dA = pk2(xa, xa), dB = pk2(xb, xb);
    #pragma unroll
    for (int t = 0; t < NP; t++) {
        float xc = sx[2 * t + 2];
        float xd = sx[2 * t + 3];
        unsigned long long dC = pk2(xc, xc), dD = pk2(xd, xd);
        uint32_t mask = 0;
        #pragma unroll
        for (int p = 0; p < 8; p++) {
            unsigned long long y0 = ffma2(dA, Wp[p][0],
                                    ffma2(dB, Wp[p][1],
                                    ffma2(dC, Wp[p][2], Bp[p])));
            unsigned long long y1 = ffma2(dB, Wp[p][0],
                                    ffma2(dC, Wp[p][1],
                                    ffma2(dD, Wp[p][2], Bp[p])));
            float a0, b0, a1, b1;
            unpk2(y0, a0, b0);
            unpk2(y1, a1, b1);
            if (fmaxf(a0, a1) > 0.f) mask |= (1u << (2 * p));
            if (fmaxf(b0, b1) > 0.f) mask |= (1u << (2 * p + 1));
        }
        constexpr bool dummy = true; (void)dummy;
        if ((GBASE + t) & 1) a[(GBASE + t) >> 1] = acc | (mask << 16);
        else                 acc = mask;
        dA = dC; dB = dD;
    }
}

// ---------------------------------------------------------------------------
// fused kernel: warp owns 32 rows; bits in registers; wbits in smem.
// ---------------------------------------------------------------------------
__global__ void __launch_bounds__(TPB, 4)
wavebnn_fused(const float* __restrict__ xA,  const float* __restrict__ xD3,
              const float* __restrict__ xD2, const float* __restrict__ xD1,
              const float* __restrict__ fc2b,
              float* __restrict__ out, int rows)
{
    extern __shared__ __align__(16) char dynsmem[];
    float*    s_stage = (float*)dynsmem;                      // [4][2][RPB*XST]
    uint32_t* s_wb    = (uint32_t*)(dynsmem + STG_BYTES);     // [FC1N*NWPAD]

    int tid  = threadIdx.x;
    int wid  = tid >> 5;
    int lane = tid & 31;
    int rowbase = blockIdx.x * TPB + wid * RPB;
    int row = rowbase + lane;

    float* b0 = s_stage + (wid * 2 + 0) * (RPB * XST);
    float* b1 = s_stage + (wid * 2 + 1) * (RPB * XST);
    const float* sx0 = &b0[lane * XST];
    const float* sx1 = &b1[lane * XST];

    // prologue staging (cp.async groups 0 and 1 in flight)
    stage32<24, 24>(b0, xA,  rowbase, 0, lane, rows); CP_COMMIT();
    stage32<24, 24>(b1, xD3, rowbase, 0, lane, rows); CP_COMMIT();

    // cooperative wbits copy to smem (regular LDG->STS; one barrier total)
    {
        const uint4* src = reinterpret_cast<const uint4*>(d_wbits);
        uint4* dst = reinterpret_cast<uint4*>(s_wb);
        #pragma unroll
        for (int i = tid; i < FC1N * NWPAD / 4; i += TPB) dst[i] = __ldg(&src[i]);
    }
    __syncthreads();

    uint32_t a[NWORDS];
    uint32_t acc = 0;
    unsigned long long Wp[8][3], Bp[8];

    // chunk 0: A3 g0-10
    CP_WAIT1(); __syncwarp();
    load_branch_g(0, Wp, Bp);
    run_chunk<11, 0>(sx0, Wp, Bp, a, acc);
    __syncwarp();
    stage32<24, 47>(b0, xD2, rowbase, 0, lane, rows); CP_COMMIT();   // chunk 2

    // chunk 1: D3 g11-21
    CP_WAIT1(); __syncwarp();
    load_branch_g(1, Wp, Bp);
    run_chunk<11, 11>(sx1, Wp, Bp, a, acc);
    __syncwarp();
    stage32<24, 47>(b1, xD2, rowbase, 22, lane, rows); CP_COMMIT();  // chunk 3

    // chunk 2: D2 g22-32
    CP_WAIT1(); __syncwarp();
    load_branch_g(2, Wp, Bp);
    run_chunk<11, 22>(sx0, Wp, Bp, a, acc);
    __syncwarp();
    stage32<26, 94>(b0, xD1, rowbase, 0, lane, rows); CP_COMMIT();   // chunk 4

    // chunk 3: D2 g33-43
    CP_WAIT1(); __syncwarp();
    run_chunk<11, 33>(sx1, Wp, Bp, a, acc);
    __syncwarp();
    stage32<26, 94>(b1, xD1, rowbase, 24, lane, rows); CP_COMMIT();  // chunk 5

    // chunk 4: D1 g44-55
    CP_WAIT1(); __syncwarp();
    load_branch_g(3, Wp, Bp);
    run_chunk<12, 44>(sx0, Wp, Bp, a, acc);
    __syncwarp();
    stage32<24, 94>(b0, xD1, rowbase, 48, lane, rows); CP_COMMIT();  // chunk 6

    // chunk 5: D1 g56-67
    CP_WAIT1(); __syncwarp();
    run_chunk<12, 56>(sx1, Wp, Bp, a, acc);
    __syncwarp();
    stage32<24, 94>(b1, xD1, rowbase, 70, lane, rows); CP_COMMIT();  // chunk 7

    // chunk 6: D1 g68-78
    CP_WAIT1(); __syncwarp();
    run_chunk<11, 68>(sx0, Wp, Bp, a, acc);

    // chunk 7: D1 g79-89
    CP_WAIT0(); __syncwarp();
    run_chunk<11, 79>(sx1, Wp, Bp, a, acc);
    // a[0..44] complete (ends at odd g89)

    // ---- FC phase: weights via broadcast LDS.128 from smem ----
    unsigned long long o01 = pk2(__ldg(&fc2b[0]), __ldg(&fc2b[1]));
    unsigned long long o23 = pk2(__ldg(&fc2b[2]), __ldg(&fc2b[3]));
    float o4 = __ldg(&fc2b[4]);

    #pragma unroll 4
    for (int j = 0; j < FC1N; j++) {
        const uint4* wj = reinterpret_cast<const uint4*>(&s_wb[j * NWPAD]);
        int s = 0;
        #pragma unroll
        for (int q = 0; q < (NWORDS - 1) / 4 + 1; q++) {   // 12 loads, last uses a[44] only
            uint4 wv = wj[q];
            if (q < 11) {
                s += __popc(a[4 * q + 0] ^ wv.x) + __popc(a[4 * q + 1] ^ wv.y)
                   + __popc(a[4 * q + 2] ^ wv.z) + __popc(a[4 * q + 3] ^ wv.w);
            } else {
                s += __popc(a[44] ^ wv.x);                 // words 45-47 padded zero
            }
        }
        float d = (float)(1440 - 2 * s);                   // exact integer dot
        float2 ab = __ldg(&d_AB1[j]);
        float val = fmaf(d, ab.x, ab.y);
        float sg = (val > 0.0f) ? 1.0f : -1.0f;
        unsigned long long sgd = pk2(sg, sg);
        const unsigned long long* w2p =
            reinterpret_cast<const unsigned long long*>(&d_w2t[j * 8]);
        o01 = ffma2(sgd, __ldg(&w2p[0]), o01);
        o23 = ffma2(sgd, __ldg(&w2p[1]), o23);
        o4  = fmaf(sg, __ldg(&d_w2t[j * 8 + 4]), o4);
    }

    if (row < rows) {
        float r0, r1, r2, r3;
        unpk2(o01, r0, r1);
        unpk2(o23, r2, r3);
        float* op = out + (size_t)row * FC2N;
        op[0] = r0; op[1] = r1; op[2] = r2; op[3] = r3; op[4] = o4;
    }
}

// ---------------------------------------------------------------------------
// launch: detect input ordering from sizes (interleaved dict order vs grouped)
// ---------------------------------------------------------------------------
extern "C" void kernel_launch(void* const* d_in, const int* in_sizes, int n_in,
                              void* d_out, int out_size)
{
    const float *xA, *xD3, *xD2, *xD1;
    const float *wA,*gA,*bA,*mA,*vA, *wB,*gB,*bB,*mB,*vB;
    const float *wC,*gC,*bC,*mC,*vC, *wD,*gD,*bD,*mD,*vD;
    const float *fc1w,*g1,*b1,*m1,*v1,*fc2w,*fc2b;

    bool interleaved = (in_sizes[1] != in_sizes[0]);

    if (interleaved) {
        xA  = (const float*)d_in[0];
        wA  = (const float*)d_in[1];  gA = (const float*)d_in[2];
        bA  = (const float*)d_in[3];  mA = (const float*)d_in[4];  vA = (const float*)d_in[5];
        xD3 = (const float*)d_in[6];
        wB  = (const float*)d_in[7];  gB = (const float*)d_in[8];
        bB  = (const float*)d_in[9];  mB = (const float*)d_in[10]; vB = (const float*)d_in[11];
        xD2 = (const float*)d_in[12];
        wC  = (const float*)d_in[13]; gC = (const float*)d_in[14];
        bC  = (const float*)d_in[15]; mC = (const float*)d_in[16]; vC = (const float*)d_in[17];
        xD1 = (const float*)d_in[18];
        wD  = (const float*)d_in[19]; gD = (const float*)d_in[20];
        bD  = (const float*)d_in[21]; mD = (const float*)d_in[22]; vD = (const float*)d_in[23];
        fc1w = (const float*)d_in[24];
        g1 = (const float*)d_in[25]; b1 = (const float*)d_in[26];
        m1 = (const float*)d_in[27]; v1 = (const float*)d_in[28];
        fc2w = (const float*)d_in[29]; fc2b = (const float*)d_in[30];
    } else {
        xA  = (const float*)d_in[0];
        xD3 = (const float*)d_in[1];
        xD2 = (const float*)d_in[2];
        xD1 = (const float*)d_in[3];
        wA  = (const float*)d_in[4];  gA = (const float*)d_in[5];
        bA  = (const float*)d_in[6];  mA = (const float*)d_in[7];  vA = (const float*)d_in[8];
        wB  = (const float*)d_in[9];  gB = (const float*)d_in[10];
        bB  = (const float*)d_in[11]; mB = (const float*)d_in[12]; vB = (const float*)d_in[13];
        wC  = (const float*)d_in[14]; gC = (const float*)d_in[15];
        bC  = (const float*)d_in[16]; mC = (const float*)d_in[17]; vC = (const float*)d_in[18];
        wD  = (const float*)d_in[19]; gD = (const float*)d_in[20];
        bD  = (const float*)d_in[21]; mD = (const float*)d_in[22]; vD = (const float*)d_in[23];
        fc1w = (const float*)d_in[24];
        g1 = (const float*)d_in[25]; b1 = (const float*)d_in[26];
        m1 = (const float*)d_in[27]; v1 = (const float*)d_in[28];
        fc2w = (const float*)d_in[29]; fc2b = (const float*)d_in[30];
    }

    int rows = in_sizes[0] / 24;

    cudaFuncSetAttribute(wavebnn_fused,
                         cudaFuncAttributeMaxDynamicSharedMemorySize, DYN_SMEM);

    prep_all<<<NBITBLK + 1, 256>>>(wA, gA, bA, mA, vA,
                                   wB, gB, bB, mB, vB,
                                   wC, gC, bC, mC, vC,
                                   wD, gD, bD, mD, vD,
                                   g1, b1, m1, v1, fc1w, fc2w);
    wavebnn_fused<<<(rows + TPB - 1) / TPB, TPB, DYN_SMEM>>>(
        xA, xD3, xD2, xD1, fc2b, (float*)d_out, rows);
}

// round 15
// speedup vs baseline: 1.1946x; 1.1946x over previous
#include <cuda_runtime.h>
#include <cstdint>

// ---------------------------------------------------------------------------
// WaveBNN R15: R11 register shape, TPB=256 (8 warps x 32 rows), XST=25 with
// 9-chunk schedule, wbits staged in smem (FC via broadcast LDS.128), bits in
// smem stride 45. 2 blocks/SM = 16 warps/SM, single wave. One block barrier.
// ---------------------------------------------------------------------------

#define OUTCH 16
#define NWORDS 45
#define NWPAD 48
#define FC1N 64
#define FC2N 5
#define RPB 32               // rows per warp
#define NWARP 8
#define TPB (NWARP * 32)     // 256 threads -> 256 rows per block
#define XST 25               // staging stride (odd -> conflict-free; max 24 cols)
#define NBITBLK 384          // prep: 3072 word-warps / 8 warps per block
#define STG_BYTES (NWARP * 2 * RPB * XST * 4)       // 51200
#define BIT_BYTES (TPB * NWORDS * 4)                // 46080
#define WB_BYTES  (FC1N * NWPAD * 4)                // 12288
#define DYN_SMEM  (STG_BYTES + BIT_BYTES + WB_BYTES) // 109568

// device scratch (no allocation allowed)
__device__ uint32_t           d_wbits[FC1N * NWPAD];
__device__ unsigned long long d_convWp[4 * 8 * 3];   // packed (W[2p],W[2p+1])*A
__device__ unsigned long long d_convBp[4 * 8];       // packed folded bias pairs
__device__ float2             d_AB1[FC1N];           // (A1, B1) per j
__device__ float              d_w2t[FC1N * 8];       // transposed fc2 w, padded

// ---------------- PTX helpers ----------------
__device__ __forceinline__ unsigned long long pk2(float lo, float hi) {
    unsigned long long d;
    asm("mov.b64 %0, {%1, %2};" : "=l"(d) : "f"(lo), "f"(hi));
    return d;
}
__device__ __forceinline__ void unpk2(unsigned long long v, float& lo, float& hi) {
    asm("mov.b64 {%0, %1}, %2;" : "=f"(lo), "=f"(hi) : "l"(v));
}
__device__ __forceinline__ unsigned long long ffma2(
    unsigned long long a, unsigned long long b, unsigned long long c) {
    unsigned long long d;
    asm("fma.rn.f32x2 %0, %1, %2, %3;" : "=l"(d) : "l"(a), "l"(b), "l"(c));
    return d;
}
__device__ __forceinline__ void cp_async4(uint32_t saddr, const float* gaddr) {
    asm volatile("cp.async.ca.shared.global [%0], [%1], 4;" :: "r"(saddr), "l"(gaddr));
}
#define CP_COMMIT() asm volatile("cp.async.commit_group;")
#define CP_WAIT1()  asm volatile("cp.async.wait_group 1;")
#define CP_WAIT0()  asm volatile("cp.async.wait_group 0;")

// ---------------------------------------------------------------------------
// prep: blocks 0..NBITBLK-1 pack fc1 bits via ballot; block NBITBLK folds
// BN constants + packs AB1 + transposes fc2w.
// ---------------------------------------------------------------------------
__global__ void prep_all(
    const float* w0, const float* g0, const float* b0, const float* m0, const float* v0,
    const float* w1, const float* g1b, const float* b1b, const float* m1b, const float* v1b,
    const float* w2, const float* g2, const float* b2, const float* m2, const float* v2,
    const float* w3, const float* g3, const float* b3, const float* m3, const float* v3,
    const float* g1, const float* b1, const float* m1, const float* v1,
    const float* fc1w, const float* fc2w)
{
    int tid = threadIdx.x;
    if (blockIdx.x == NBITBLK) {
        if (tid < 64) {
            int br = tid >> 4, c = tid & 15;
            int p = c >> 1, h = c & 1;
            const float* ws[4] = {w0, w1, w2, w3};
            const float* gs[4] = {g0, g1b, g2, g3};
            const float* bs[4] = {b0, b1b, b2, b3};
            const float* ms[4] = {m0, m1b, m2, m3};
            const float* vs[4] = {v0, v1b, v2, v3};
            double A = (double)gs[br][c] * rsqrt((double)vs[br][c] + 1e-5);
            float Af = (float)A;
            float* bp = (float*)d_convBp;
            bp[(br * 8 + p) * 2 + h] = (float)((double)bs[br][c] - (double)ms[br][c] * A);
            float* wp = (float*)d_convWp;
            #pragma unroll
            for (int k = 0; k < 3; k++) {
                float wv = ws[br][c * 3 + k];
                float s = (wv > 0.f) ? 1.f : ((wv < 0.f) ? -1.f : 0.f);
                wp[(((br * 8 + p) * 3) + k) * 2 + h] = s * Af;
            }
        } else if (tid < 128) {
            int j = tid - 64;
            double A = (double)g1[j] * rsqrt((double)v1[j] + 1e-5);
            d_AB1[j] = make_float2((float)A,
                                   (float)((double)b1[j] - (double)m1[j] * A));
        }
        for (int idx = tid; idx < FC1N * 8; idx += 256) {
            int j = idx >> 3, i = idx & 7;
            d_w2t[idx] = (i < FC2N) ? fc2w[i * FC1N + j] : 0.f;
        }
        return;
    }
    // bit packing: global warp = (j, wi); lane = bit index
    int gwarp = blockIdx.x * 8 + (tid >> 5);
    int lane = tid & 31;
    if (gwarp >= FC1N * NWPAD) return;
    int j = gwarp / NWPAD, wi = gwarp % NWPAD;
    int gb = wi * 32 + lane;
    bool pred = false;
    if (gb < 1440) {
        const int OFF[4] = {0, 176, 352, 704};
        const int LPa[4] = {11, 11, 22, 46};
        int grp = gb >> 4, c = gb & 15, br, t;
        if (grp < 11)      { br = 0; t = grp; }
        else if (grp < 22) { br = 1; t = grp - 11; }
        else if (grp < 44) { br = 2; t = grp - 22; }
        else               { br = 3; t = grp - 44; }
        int col = OFF[br] + c * LPa[br] + t;
        pred = fc1w[j * 1440 + col] > 0.f;
    }
    uint32_t wrd = __ballot_sync(0xffffffffu, pred);
    if (lane == 0) d_wbits[j * NWPAD + wi] = wrd;
}

// ---------------------------------------------------------------------------
// fused kernel helpers
// ---------------------------------------------------------------------------
// warp-scope stage of RPB x COLS slab (pitch L) into sdst (stride XST)
template<int COLS, int L>
__device__ __forceinline__ void stage32(
    float* __restrict__ sdst, const float* __restrict__ xg,
    int rowbase, int c0, int lane, int rows)
{
    uint32_t sb = (uint32_t)__cvta_generic_to_shared(sdst);
    #pragma unroll
    for (int i = lane; i < RPB * COLS; i += 32) {
        int r = i / COLS, c = i - r * COLS;
        int rr = min(rowbase + r, rows - 1);
        cp_async4(sb + (uint32_t)(r * XST + c) * 4, xg + (size_t)rr * L + c0 + c);
    }
}

__device__ __forceinline__ void load_branch_g(
    int br, unsigned long long (&Wp)[8][3], unsigned long long (&Bp)[8])
{
    #pragma unroll
    for (int p = 0; p < 8; p++) {
        Wp[p][0] = d_convWp[(br * 8 + p) * 3 + 0];
        Wp[p][1] = d_convWp[(br * 8 + p) * 3 + 1];
        Wp[p][2] = d_convWp[(br * 8 + p) * 3 + 2];
        Bp[p]    = d_convBp[br * 8 + p];
    }
}

// conv NP pooled groups; odd group completes a 32-bit word -> smem store
template<int NP>
__device__ __forceinline__ void run_chunk(
    const float* __restrict__ sx,
    const unsigned long long (&Wp)[8][3], const unsigned long long (&Bp)[8],
    int gbase, uint32_t* __restrict__ mybits, uint32_t& acc)
{
    float xa = sx[0], xb = sx[1];
    unsigned long long dA = pk2(xa, xa), dB = pk2(xb, xb);
    #pragma unroll 2
    for (int t = 0; t < NP; t++) {
        float xc = sx[2 * t + 2];
        float xd = sx[2 * t + 3];
        unsigned long long dC = pk2(xc, xc), dD = pk2(xd, xd);
        uint32_t mask = 0;
        #pragma unroll
        for (int p = 0; p < 8; p++) {
            unsigned long long y0 = ffma2(dA, Wp[p][0],
                                    ffma2(dB, Wp[p][1],
                                    ffma2(dC, Wp[p][2], Bp[p])));
            unsigned long long y1 = ffma2(dB, Wp[p][0],
                                    ffma2(dC, Wp[p][1],
                                    ffma2(dD, Wp[p][2], Bp[p])));
            float a0, b0, a1, b1;
            unpk2(y0, a0, b0);
            unpk2(y1, a1, b1);
            if (fmaxf(a0, a1) > 0.f) mask |= (1u << (2 * p));
            if (fmaxf(b0, b1) > 0.f) mask |= (1u << (2 * p + 1));
        }
        int g = gbase + t;
        if (g & 1) mybits[g >> 1] = acc | (mask << 16);
        else       acc = mask;
        dA = dC; dB = dD;
    }
}

// ---------------------------------------------------------------------------
// fused kernel: 8 warps x 32 rows; warp-private cp.async; one block barrier.
// ---------------------------------------------------------------------------
__global__ void __launch_bounds__(TPB, 2)
wavebnn_fused(const float* __restrict__ xA,  const float* __restrict__ xD3,
              const float* __restrict__ xD2, const float* __restrict__ xD1,
              const float* __restrict__ fc2b,
              float* __restrict__ out, int rows)
{
    extern __shared__ __align__(16) char dynsmem[];
    float*    s_stage = (float*)dynsmem;                             // [8][2][RPB*XST]
    uint32_t* s_bits  = (uint32_t*)(dynsmem + STG_BYTES);            // [TPB*NWORDS]
    uint32_t* s_wb    = (uint32_t*)(dynsmem + STG_BYTES + BIT_BYTES);// [FC1N*NWPAD]

    int tid  = threadIdx.x;
    int wid  = tid >> 5;
    int lane = tid & 31;
    int rowbase = blockIdx.x * TPB + wid * RPB;   // this warp's 32 rows
    int row = rowbase + lane;

    float* b0 = s_stage + (wid * 2 + 0) * (RPB * XST);
    float* b1 = s_stage + (wid * 2 + 1) * (RPB * XST);
    const float* sx0 = &b0[lane * XST];
    const float* sx1 = &b1[lane * XST];
    uint32_t* mybits = &s_bits[tid * NWORDS];
    uint32_t acc = 0;
    unsigned long long Wp[8][3], Bp[8];

    // prologue: chunks 0 (A3) and 1 (D3) in flight
    stage32<24, 24>(b0, xA,  rowbase, 0, lane, rows); CP_COMMIT();
    stage32<24, 24>(b1, xD3, rowbase, 0, lane, rows); CP_COMMIT();

    // cooperative wbits copy (LDG->STS; single barrier of the kernel)
    {
        const uint4* src = reinterpret_cast<const uint4*>(d_wbits);
        uint4* dst = reinterpret_cast<uint4*>(s_wb);
        #pragma unroll
        for (int i = tid; i < FC1N * NWPAD / 4; i += TPB) dst[i] = __ldg(&src[i]);
    }
    __syncthreads();

    // chunk 0: A3 g0-10
    CP_WAIT1(); __syncwarp();
    load_branch_g(0, Wp, Bp);
    run_chunk<11>(sx0, Wp, Bp, 0, mybits, acc);
    __syncwarp();
    stage32<24, 47>(b0, xD2, rowbase, 0, lane, rows); CP_COMMIT();   // chunk 2

    // chunk 1: D3 g11-21
    CP_WAIT1(); __syncwarp();
    load_branch_g(1, Wp, Bp);
    run_chunk<11>(sx1, Wp, Bp, 11, mybits, acc);
    __syncwarp();
    stage32<24, 47>(b1, xD2, rowbase, 22, lane, rows); CP_COMMIT();  // chunk 3

    // chunk 2: D2 g22-32
    CP_WAIT1(); __syncwarp();
    load_branch_g(2, Wp, Bp);
    run_chunk<11>(sx0, Wp, Bp, 22, mybits, acc);
    __syncwarp();
    stage32<24, 94>(b0, xD1, rowbase, 0, lane, rows); CP_COMMIT();   // chunk 4

    // chunk 3: D2 g33-43
    CP_WAIT1(); __syncwarp();
    run_chunk<11>(sx1, Wp, Bp, 33, mybits, acc);
    __syncwarp();
    stage32<24, 94>(b1, xD1, rowbase, 22, lane, rows); CP_COMMIT();  // chunk 5

    // chunk 4: D1 g44-54 (cols 0-23)
    CP_WAIT1(); __syncwarp();
    load_branch_g(3, Wp, Bp);
    run_chunk<11>(sx0, Wp, Bp, 44, mybits, acc);
    __syncwarp();
    stage32<24, 94>(b0, xD1, rowbase, 44, lane, rows); CP_COMMIT();  // chunk 6

    // chunk 5: D1 g55-65 (cols 22-45)
    CP_WAIT1(); __syncwarp();
    run_chunk<11>(sx1, Wp, Bp, 55, mybits, acc);
    __syncwarp();
    stage32<24, 94>(b1, xD1, rowbase, 66, lane, rows); CP_COMMIT();  // chunk 7

    // chunk 6: D1 g66-76 (cols 44-67)
    CP_WAIT1(); __syncwarp();
    run_chunk<11>(sx0, Wp, Bp, 66, mybits, acc);
    __syncwarp();
    stage32<6, 94>(b0, xD1, rowbase, 88, lane, rows); CP_COMMIT();   // chunk 8

    // chunk 7: D1 g77-87 (cols 66-89)
    CP_WAIT1(); __syncwarp();
    run_chunk<11>(sx1, Wp, Bp, 77, mybits, acc);

    // chunk 8: D1 g88-89 (cols 88-93) — newest group is ours: wait 0
    CP_WAIT0(); __syncwarp();
    run_chunk<2>(sx0, Wp, Bp, 88, mybits, acc);
    // all 45 words written (ends at odd g89)

    // ---- FC phase: own bits -> regs; weights via broadcast LDS.128 ----
    uint32_t a[NWPAD];
    #pragma unroll
    for (int w = 0; w < NWORDS; w++) a[w] = mybits[w];
    a[45] = 0; a[46] = 0; a[47] = 0;

    unsigned long long o01 = pk2(__ldg(&fc2b[0]), __ldg(&fc2b[1]));
    unsigned long long o23 = pk2(__ldg(&fc2b[2]), __ldg(&fc2b[3]));
    float o4 = __ldg(&fc2b[4]);

    #pragma unroll 2
    for (int j = 0; j < FC1N; j++) {
        const uint4* wj = reinterpret_cast<const uint4*>(&s_wb[j * NWPAD]);
        int s = 0;
        #pragma unroll
        for (int q = 0; q < NWPAD / 4; q++) {
            uint4 wv = wj[q];
            s += __popc(a[4 * q + 0] ^ wv.x) + __popc(a[4 * q + 1] ^ wv.y)
               + __popc(a[4 * q + 2] ^ wv.z) + __popc(a[4 * q + 3] ^ wv.w);
        }
        float d = (float)(1440 - 2 * s);               // exact integer dot
        float2 ab = __ldg(&d_AB1[j]);
        float val = fmaf(d, ab.x, ab.y);
        float sg = (val > 0.0f) ? 1.0f : -1.0f;
        unsigned long long sgd = pk2(sg, sg);
        const unsigned long long* w2p =
            reinterpret_cast<const unsigned long long*>(&d_w2t[j * 8]);
        o01 = ffma2(sgd, __ldg(&w2p[0]), o01);
        o23 = ffma2(sgd, __ldg(&w2p[1]), o23);
        o4  = fmaf(sg, __ldg(&d_w2t[j * 8 + 4]), o4);
    }

    if (row < rows) {
        float r0, r1, r2, r3;
        unpk2(o01, r0, r1);
        unpk2(o23, r2, r3);
        float* op = out + (size_t)row * FC2N;
        op[0] = r0; op[1] = r1; op[2] = r2; op[3] = r3; op[4] = o4;
    }
}

// ---------------------------------------------------------------------------
// launch: detect input ordering from sizes (interleaved dict order vs grouped)
// ---------------------------------------------------------------------------
extern "C" void kernel_launch(void* const* d_in, const int* in_sizes, int n_in,
                              void* d_out, int out_size)
{
    const float *xA, *xD3, *xD2, *xD1;
    const float *wA,*gA,*bA,*mA,*vA, *wB,*gB,*bB,*mB,*vB;
    const float *wC,*gC,*bC,*mC,*vC, *wD,*gD,*bD,*mD,*vD;
    const float *fc1w,*g1,*b1,*m1,*v1,*fc2w,*fc2b;

    bool interleaved = (in_sizes[1] != in_sizes[0]);

    if (interleaved) {
        xA  = (const float*)d_in[0];
        wA  = (const float*)d_in[1];  gA = (const float*)d_in[2];
        bA  = (const float*)d_in[3];  mA = (const float*)d_in[4];  vA = (const float*)d_in[5];
        xD3 = (const float*)d_in[6];
        wB  = (const float*)d_in[7];  gB = (const float*)d_in[8];
        bB  = (const float*)d_in[9];  mB = (const float*)d_in[10]; vB = (const float*)d_in[11];
        xD2 = (const float*)d_in[12];
        wC  = (const float*)d_in[13]; gC = (const float*)d_in[14];
        bC  = (const float*)d_in[15]; mC = (const float*)d_in[16]; vC = (const float*)d_in[17];
        xD1 = (const float*)d_in[18];
        wD  = (const float*)d_in[19]; gD = (const float*)d_in[20];
        bD  = (const float*)d_in[21]; mD = (const float*)d_in[22]; vD = (const float*)d_in[23];
        fc1w = (const float*)d_in[24];
        g1 = (const float*)d_in[25]; b1 = (const float*)d_in[26];
        m1 = (const float*)d_in[27]; v1 = (const float*)d_in[28];
        fc2w = (const float*)d_in[29]; fc2b = (const float*)d_in[30];
    } else {
        xA  = (const float*)d_in[0];
        xD3 = (const float*)d_in[1];
        xD2 = (const float*)d_in[2];
        xD1 = (const float*)d_in[3];
        wA  = (const float*)d_in[4];  gA = (const float*)d_in[5];
        bA  = (const float*)d_in[6];  mA = (const float*)d_in[7];  vA = (const float*)d_in[8];
        wB  = (const float*)d_in[9];  gB = (const float*)d_in[10];
        bB  = (const float*)d_in[11]; mB = (const float*)d_in[12]; vB = (const float*)d_in[13];
        wC  = (const float*)d_in[14]; gC = (const float*)d_in[15];
        bC  = (const float*)d_in[16]; mC = (const float*)d_in[17]; vC = (const float*)d_in[18];
        wD  = (const float*)d_in[19]; gD = (const float*)d_in[20];
        bD  = (const float*)d_in[21]; mD = (const float*)d_in[22]; vD = (const float*)d_in[23];
        fc1w = (const float*)d_in[24];
        g1 = (const float*)d_in[25]; b1 = (const float*)d_in[26];
        m1 = (const float*)d_in[27]; v1 = (const float*)d_in[28];
        fc2w = (const float*)d_in[29]; fc2b = (const float*)d_in[30];
    }

    int rows = in_sizes[0] / 24;

    cudaFuncSetAttribute(wavebnn_fused,
                         cudaFuncAttributeMaxDynamicSharedMemorySize, DYN_SMEM);

    prep_all<<<NBITBLK + 1, 256>>>(wA, gA, bA, mA, vA,
                                   wB, gB, bB, mB, vB,
                                   wC, gC, bC, mC, vC,
                                   wD, gD, bD, mD, vD,
                                   g1, b1, m1, v1, fc1w, fc2w);
    wavebnn_fused<<<(rows + TPB - 1) / TPB, TPB, DYN_SMEM>>>(
        xA, xD3, xD2, xD1, fc2b, (float*)d_out, rows);
}

// round 16
// speedup vs baseline: 1.2406x; 1.0385x over previous
#include <cuda_runtime.h>
#include <cstdint>

// ---------------------------------------------------------------------------
// WaveBNN R16: R15 + (1) XST=26, conv inner loads via LDS.64 float2 pairs,
// (2) FC1 j-unroll 4, (3) FC popcount trimmed to exactly 45 words.
// 8 warps x 32 rows, warp-private cp.async, wbits in smem, one block barrier.
// ---------------------------------------------------------------------------

#define OUTCH 16
#define NWORDS 45
#define NWPAD 48
#define FC1N 64
#define FC2N 5
#define RPB 32               // rows per warp
#define NWARP 8
#define TPB (NWARP * 32)     // 256 threads -> 256 rows per block
#define XST 26               // staging stride (even -> 8B-aligned lane bases)
#define NBITBLK 384          // prep: 3072 word-warps / 8 warps per block
#define STG_BYTES (NWARP * 2 * RPB * XST * 4)        // 53248
#define BIT_BYTES (TPB * NWORDS * 4)                 // 46080
#define WB_BYTES  (FC1N * NWPAD * 4)                 // 12288
#define DYN_SMEM  (STG_BYTES + BIT_BYTES + WB_BYTES) // 111616

// device scratch (no allocation allowed)
__device__ uint32_t           d_wbits[FC1N * NWPAD];
__device__ unsigned long long d_convWp[4 * 8 * 3];   // packed (W[2p],W[2p+1])*A
__device__ unsigned long long d_convBp[4 * 8];       // packed folded bias pairs
__device__ float2             d_AB1[FC1N];           // (A1, B1) per j
__device__ float              d_w2t[FC1N * 8];       // transposed fc2 w, padded

// ---------------- PTX helpers ----------------
__device__ __forceinline__ unsigned long long pk2(float lo, float hi) {
    unsigned long long d;
    asm("mov.b64 %0, {%1, %2};" : "=l"(d) : "f"(lo), "f"(hi));
    return d;
}
__device__ __forceinline__ void unpk2(unsigned long long v, float& lo, float& hi) {
    asm("mov.b64 {%0, %1}, %2;" : "=f"(lo), "=f"(hi) : "l"(v));
}
__device__ __forceinline__ unsigned long long ffma2(
    unsigned long long a, unsigned long long b, unsigned long long c) {
    unsigned long long d;
    asm("fma.rn.f32x2 %0, %1, %2, %3;" : "=l"(d) : "l"(a), "l"(b), "l"(c));
    return d;
}
__device__ __forceinline__ void cp_async4(uint32_t saddr, const float* gaddr) {
    asm volatile("cp.async.ca.shared.global [%0], [%1], 4;" :: "r"(saddr), "l"(gaddr));
}
#define CP_COMMIT() asm volatile("cp.async.commit_group;")
#define CP_WAIT1()  asm volatile("cp.async.wait_group 1;")
#define CP_WAIT0()  asm volatile("cp.async.wait_group 0;")

// ---------------------------------------------------------------------------
// prep: blocks 0..NBITBLK-1 pack fc1 bits via ballot; block NBITBLK folds
// BN constants + packs AB1 + transposes fc2w.
// ---------------------------------------------------------------------------
__global__ void prep_all(
    const float* w0, const float* g0, const float* b0, const float* m0, const float* v0,
    const float* w1, const float* g1b, const float* b1b, const float* m1b, const float* v1b,
    const float* w2, const float* g2, const float* b2, const float* m2, const float* v2,
    const float* w3, const float* g3, const float* b3, const float* m3, const float* v3,
    const float* g1, const float* b1, const float* m1, const float* v1,
    const float* fc1w, const float* fc2w)
{
    int tid = threadIdx.x;
    if (blockIdx.x == NBITBLK) {
        if (tid < 64) {
            int br = tid >> 4, c = tid & 15;
            int p = c >> 1, h = c & 1;
            const float* ws[4] = {w0, w1, w2, w3};
            const float* gs[4] = {g0, g1b, g2, g3};
            const float* bs[4] = {b0, b1b, b2, b3};
            const float* ms[4] = {m0, m1b, m2, m3};
            const float* vs[4] = {v0, v1b, v2, v3};
            double A = (double)gs[br][c] * rsqrt((double)vs[br][c] + 1e-5);
            float Af = (float)A;
            float* bp = (float*)d_convBp;
            bp[(br * 8 + p) * 2 + h] = (float)((double)bs[br][c] - (double)ms[br][c] * A);
            float* wp = (float*)d_convWp;
            #pragma unroll
            for (int k = 0; k < 3; k++) {
                float wv = ws[br][c * 3 + k];
                float s = (wv > 0.f) ? 1.f : ((wv < 0.f) ? -1.f : 0.f);
                wp[(((br * 8 + p) * 3) + k) * 2 + h] = s * Af;
            }
        } else if (tid < 128) {
            int j = tid - 64;
            double A = (double)g1[j] * rsqrt((double)v1[j] + 1e-5);
            d_AB1[j] = make_float2((float)A,
                                   (float)((double)b1[j] - (double)m1[j] * A));
        }
        for (int idx = tid; idx < FC1N * 8; idx += 256) {
            int j = idx >> 3, i = idx & 7;
            d_w2t[idx] = (i < FC2N) ? fc2w[i * FC1N + j] : 0.f;
        }
        return;
    }
    // bit packing: global warp = (j, wi); lane = bit index
    int gwarp = blockIdx.x * 8 + (tid >> 5);
    int lane = tid & 31;
    if (gwarp >= FC1N * NWPAD) return;
    int j = gwarp / NWPAD, wi = gwarp % NWPAD;
    int gb = wi * 32 + lane;
    bool pred = false;
    if (gb < 1440) {
        const int OFF[4] = {0, 176, 352, 704};
        const int LPa[4] = {11, 11, 22, 46};
        int grp = gb >> 4, c = gb & 15, br, t;
        if (grp < 11)      { br = 0; t = grp; }
        else if (grp < 22) { br = 1; t = grp - 11; }
        else if (grp < 44) { br = 2; t = grp - 22; }
        else               { br = 3; t = grp - 44; }
        int col = OFF[br] + c * LPa[br] + t;
        pred = fc1w[j * 1440 + col] > 0.f;
    }
    uint32_t wrd = __ballot_sync(0xffffffffu, pred);
    if (lane == 0) d_wbits[j * NWPAD + wi] = wrd;
}

// ---------------------------------------------------------------------------
// fused kernel helpers
// ---------------------------------------------------------------------------
// warp-scope stage of RPB x COLS slab (pitch L) into sdst (stride XST)
template<int COLS, int L>
__device__ __forceinline__ void stage32(
    float* __restrict__ sdst, const float* __restrict__ xg,
    int rowbase, int c0, int lane, int rows)
{
    uint32_t sb = (uint32_t)__cvta_generic_to_shared(sdst);
    #pragma unroll
    for (int i = lane; i < RPB * COLS; i += 32) {
        int r = i / COLS, c = i - r * COLS;
        int rr = min(rowbase + r, rows - 1);
        cp_async4(sb + (uint32_t)(r * XST + c) * 4, xg + (size_t)rr * L + c0 + c);
    }
}

__device__ __forceinline__ void load_branch_g(
    int br, unsigned long long (&Wp)[8][3], unsigned long long (&Bp)[8])
{
    #pragma unroll
    for (int p = 0; p < 8; p++) {
        Wp[p][0] = d_convWp[(br * 8 + p) * 3 + 0];
        Wp[p][1] = d_convWp[(br * 8 + p) * 3 + 1];
        Wp[p][2] = d_convWp[(br * 8 + p) * 3 + 2];
        Bp[p]    = d_convBp[br * 8 + p];
    }
}

// conv NP pooled groups; inner loads are LDS.64 pairs (lane base 8B-aligned)
template<int NP>
__device__ __forceinline__ void run_chunk(
    const float* __restrict__ sx,
    const unsigned long long (&Wp)[8][3], const unsigned long long (&Bp)[8],
    int gbase, uint32_t* __restrict__ mybits, uint32_t& acc)
{
    float2 v0 = *reinterpret_cast<const float2*>(sx);
    float xa = v0.x, xb = v0.y;
    unsigned long long dA = pk2(xa, xa), dB = pk2(xb, xb);
    #pragma unroll 2
    for (int t = 0; t < NP; t++) {
        float2 cd = *reinterpret_cast<const float2*>(sx + 2 * t + 2);
        unsigned long long dC = pk2(cd.x, cd.x), dD = pk2(cd.y, cd.y);
        uint32_t mask = 0;
        #pragma unroll
        for (int p = 0; p < 8; p++) {
            unsigned long long y0 = ffma2(dA, Wp[p][0],
                                    ffma2(dB, Wp[p][1],
                                    ffma2(dC, Wp[p][2], Bp[p])));
            unsigned long long y1 = ffma2(dB, Wp[p][0],
                                    ffma2(dC, Wp[p][1],
                                    ffma2(dD, Wp[p][2], Bp[p])));
            float a0, b0, a1, b1;
            unpk2(y0, a0, b0);
            unpk2(y1, a1, b1);
            if (fmaxf(a0, a1) > 0.f) mask |= (1u << (2 * p));
            if (fmaxf(b0, b1) > 0.f) mask |= (1u << (2 * p + 1));
        }
        int g = gbase + t;
        if (g & 1) mybits[g >> 1] = acc | (mask << 16);
        else       acc = mask;
        dA = dC; dB = dD;
    }
}

// ---------------------------------------------------------------------------
// fused kernel: 8 warps x 32 rows; warp-private cp.async; one block barrier.
// ---------------------------------------------------------------------------
__global__ void __launch_bounds__(TPB, 2)
wavebnn_fused(const float* __restrict__ xA,  const float* __restrict__ xD3,
              const float* __restrict__ xD2, const float* __restrict__ xD1,
              const float* __restrict__ fc2b,
              float* __restrict__ out, int rows)
{
    extern __shared__ __align__(16) char dynsmem[];
    float*    s_stage = (float*)dynsmem;                             // [8][2][RPB*XST]
    uint32_t* s_bits  = (uint32_t*)(dynsmem + STG_BYTES);            // [TPB*NWORDS]
    uint32_t* s_wb    = (uint32_t*)(dynsmem + STG_BYTES + BIT_BYTES);// [FC1N*NWPAD]

    int tid  = threadIdx.x;
    int wid  = tid >> 5;
    int lane = tid & 31;
    int rowbase = blockIdx.x * TPB + wid * RPB;   // this warp's 32 rows
    int row = rowbase + lane;

    float* b0 = s_stage + (wid * 2 + 0) * (RPB * XST);
    float* b1 = s_stage + (wid * 2 + 1) * (RPB * XST);
    const float* sx0 = &b0[lane * XST];
    const float* sx1 = &b1[lane * XST];
    uint32_t* mybits = &s_bits[tid * NWORDS];
    uint32_t acc = 0;
    unsigned long long Wp[8][3], Bp[8];

    // prologue: chunks 0 (A3) and 1 (D3) in flight
    stage32<24, 24>(b0, xA,  rowbase, 0, lane, rows); CP_COMMIT();
    stage32<24, 24>(b1, xD3, rowbase, 0, lane, rows); CP_COMMIT();

    // cooperative wbits copy (LDG->STS; single barrier of the kernel)
    {
        const uint4* src = reinterpret_cast<const uint4*>(d_wbits);
        uint4* dst = reinterpret_cast<uint4*>(s_wb);
        #pragma unroll
        for (int i = tid; i < FC1N * NWPAD / 4; i += TPB) dst[i] = __ldg(&src[i]);
    }
    __syncthreads();

    // chunk 0: A3 g0-10
    CP_WAIT1(); __syncwarp();
    load_branch_g(0, Wp, Bp);
    run_chunk<11>(sx0, Wp, Bp, 0, mybits, acc);
    __syncwarp();
    stage32<24, 47>(b0, xD2, rowbase, 0, lane, rows); CP_COMMIT();   // chunk 2

    // chunk 1: D3 g11-21
    CP_WAIT1(); __syncwarp();
    load_branch_g(1, Wp, Bp);
    run_chunk<11>(sx1, Wp, Bp, 11, mybits, acc);
    __syncwarp();
    stage32<24, 47>(b1, xD2, rowbase, 22, lane, rows); CP_COMMIT();  // chunk 3

    // chunk 2: D2 g22-32
    CP_WAIT1(); __syncwarp();
    load_branch_g(2, Wp, Bp);
    run_chunk<11>(sx0, Wp, Bp, 22, mybits, acc);
    __syncwarp();
    stage32<24, 94>(b0, xD1, rowbase, 0, lane, rows); CP_COMMIT();   // chunk 4

    // chunk 3: D2 g33-43
    CP_WAIT1(); __syncwarp();
    run_chunk<11>(sx1, Wp, Bp, 33, mybits, acc);
    __syncwarp();
    stage32<24, 94>(b1, xD1, rowbase, 22, lane, rows); CP_COMMIT();  // chunk 5

    // chunk 4: D1 g44-54 (cols 0-23)
    CP_WAIT1(); __syncwarp();
    load_branch_g(3, Wp, Bp);
    run_chunk<11>(sx0, Wp, Bp, 44, mybits, acc);
    __syncwarp();
    stage32<24, 94>(b0, xD1, rowbase, 44, lane, rows); CP_COMMIT();  // chunk 6

    // chunk 5: D1 g55-65 (cols 22-45)
    CP_WAIT1(); __syncwarp();
    run_chunk<11>(sx1, Wp, Bp, 55, mybits, acc);
    __syncwarp();
    stage32<24, 94>(b1, xD1, rowbase, 66, lane, rows); CP_COMMIT();  // chunk 7

    // chunk 6: D1 g66-76 (cols 44-67)
    CP_WAIT1(); __syncwarp();
    run_chunk<11>(sx0, Wp, Bp, 66, mybits, acc);
    __syncwarp();
    stage32<6, 94>(b0, xD1, rowbase, 88, lane, rows); CP_COMMIT();   // chunk 8

    // chunk 7: D1 g77-87 (cols 66-89)
    CP_WAIT1(); __syncwarp();
    run_chunk<11>(sx1, Wp, Bp, 77, mybits, acc);

    // chunk 8: D1 g88-89 (cols 88-93) — newest group is ours: wait 0
    CP_WAIT0(); __syncwarp();
    run_chunk<2>(sx0, Wp, Bp, 88, mybits, acc);
    // all 45 words written (ends at odd g89)

    // ---- FC phase: own bits -> regs; weights via broadcast LDS.128 ----
    uint32_t a[NWORDS];
    #pragma unroll
    for (int w = 0; w < NWORDS; w++) a[w] = mybits[w];

    unsigned long long o01 = pk2(__ldg(&fc2b[0]), __ldg(&fc2b[1]));
    unsigned long long o23 = pk2(__ldg(&fc2b[2]), __ldg(&fc2b[3]));
    float o4 = __ldg(&fc2b[4]);

    #pragma unroll 4
    for (int j = 0; j < FC1N; j++) {
        const uint4* wj = reinterpret_cast<const uint4*>(&s_wb[j * NWPAD]);
        int s = 0;
        #pragma unroll
        for (int q = 0; q < 11; q++) {                 // words 0..43
            uint4 wv = wj[q];
            s += __popc(a[4 * q + 0] ^ wv.x) + __popc(a[4 * q + 1] ^ wv.y)
               + __popc(a[4 * q + 2] ^ wv.z) + __popc(a[4 * q + 3] ^ wv.w);
        }
        s += __popc(a[44] ^ s_wb[j * NWPAD + 44]);     // word 44
        float d = (float)(1440 - 2 * s);               // exact integer dot
        float2 ab = __ldg(&d_AB1[j]);
        float val = fmaf(d, ab.x, ab.y);
        float sg = (val > 0.0f) ? 1.0f : -1.0f;
        unsigned long long sgd = pk2(sg, sg);
        const unsigned long long* w2p =
            reinterpret_cast<const unsigned long long*>(&d_w2t[j * 8]);
        o01 = ffma2(sgd, __ldg(&w2p[0]), o01);
        o23 = ffma2(sgd, __ldg(&w2p[1]), o23);
        o4  = fmaf(sg, __ldg(&d_w2t[j * 8 + 4]), o4);
    }

    if (row < rows) {
        float r0, r1, r2, r3;
        unpk2(o01, r0, r1);
        unpk2(o23, r2, r3);
        float* op = out + (size_t)row * FC2N;
        op[0] = r0; op[1] = r1; op[2] = r2; op[3] = r3; op[4] = o4;
    }
}

// ---------------------------------------------------------------------------
// launch: detect input ordering from sizes (interleaved dict order vs grouped)
// ---------------------------------------------------------------------------
extern "C" void kernel_launch(void* const* d_in, const int* in_sizes, int n_in,
                              void* d_out, int out_size)
{
    const float *xA, *xD3, *xD2, *xD1;
    const float *wA,*gA,*bA,*mA,*vA, *wB,*gB,*bB,*mB,*vB;
    const float *wC,*gC,*bC,*mC,*vC, *wD,*gD,*bD,*mD,*vD;
    const float *fc1w,*g1,*b1,*m1,*v1,*fc2w,*fc2b;

    bool interleaved = (in_sizes[1] != in_sizes[0]);

    if (interleaved) {
        xA  = (const float*)d_in[0];
        wA  = (const float*)d_in[1];  gA = (const float*)d_in[2];
        bA  = (const float*)d_in[3];  mA = (const float*)d_in[4];  vA = (const float*)d_in[5];
        xD3 = (const float*)d_in[6];
        wB  = (const float*)d_in[7];  gB = (const float*)d_in[8];
        bB  = (const float*)d_in[9];  mB = (const float*)d_in[10]; vB = (const float*)d_in[11];
        xD2 = (const float*)d_in[12];
        wC  = (const float*)d_in[13]; gC = (const float*)d_in[14];
        bC  = (const float*)d_in[15]; mC = (const float*)d_in[16]; vC = (const float*)d_in[17];
        xD1 = (const float*)d_in[18];
        wD  = (const float*)d_in[19]; gD = (const float*)d_in[20];
        bD  = (const float*)d_in[21]; mD = (const float*)d_in[22]; vD = (const float*)d_in[23];
        fc1w = (const float*)d_in[24];
        g1 = (const float*)d_in[25]; b1 = (const float*)d_in[26];
        m1 = (const float*)d_in[27]; v1 = (const float*)d_in[28];
        fc2w = (const float*)d_in[29]; fc2b = (const float*)d_in[30];
    } else {
        xA  = (const float*)d_in[0];
        xD3 = (const float*)d_in[1];
        xD2 = (const float*)d_in[2];
        xD1 = (const float*)d_in[3];
        wA  = (const float*)d_in[4];  gA = (const float*)d_in[5];
        bA  = (const float*)d_in[6];  mA = (const float*)d_in[7];  vA = (const float*)d_in[8];
        wB  = (const float*)d_in[9];  gB = (const float*)d_in[10];
        bB  = (const float*)d_in[11]; mB = (const float*)d_in[12]; vB = (const float*)d_in[13];
        wC  = (const float*)d_in[14]; gC = (const float*)d_in[15];
        bC  = (const float*)d_in[16]; mC = (const float*)d_in[17]; vC = (const float*)d_in[18];
        wD  = (const float*)d_in[19]; gD = (const float*)d_in[20];
        bD  = (const float*)d_in[21]; mD = (const float*)d_in[22]; vD = (const float*)d_in[23];
        fc1w = (const float*)d_in[24];
        g1 = (const float*)d_in[25]; b1 = (const float*)d_in[26];
        m1 = (const float*)d_in[27]; v1 = (const float*)d_in[28];
        fc2w = (const float*)d_in[29]; fc2b = (const float*)d_in[30];
    }

    int rows = in_sizes[0] / 24;

    cudaFuncSetAttribute(wavebnn_fused,
                         cudaFuncAttributeMaxDynamicSharedMemorySize, DYN_SMEM);

    prep_all<<<NBITBLK + 1, 256>>>(wA, gA, bA, mA, vA,
                                   wB, gB, bB, mB, vB,
                                   wC, gC, bC, mC, vC,
                                   wD, gD, bD, mD, vD,
                                   g1, b1, m1, v1, fc1w, fc2w);
    wavebnn_fused<<<(rows + TPB - 1) / TPB, TPB, DYN_SMEM>>>(
        xA, xD3, xD2, xD1, fc2b, (float*)d_out, rows);
}